// round 3
// baseline (speedup 1.0000x reference)
#include <cuda_runtime.h>
#include <math.h>

typedef unsigned long long ull;

#define NN 50000
#define RPAD 50176
#define EE 800000
#define KH 20
#define SBLK 196          // ceil(NN/256)

// ---------------- scratch (device globals; zero-init at module load) ---------
__device__ float g_S2[(size_t)RPAD * 1344];   // L2 stack: 21 blocks of 64
__device__ float g_S3[(size_t)RPAD * 2688];   // L3 stack: 21 blocks of 128 (reused as L4 Y stack, 21 blocks of 96)
__device__ float g_P0[(size_t)RPAD * 224];    // L3 activations [N,224] / L4 act [N,96]
__device__ float g_P1[(size_t)RPAD * 96];
__device__ float g_P2[(size_t)RPAD * 96];
__device__ float g_S1[21 * RPAD];             // L1 scalar hops / L5 Y
__device__ float g_Wp2[1344 * 100];
__device__ float g_Wp3[2688 * 200];
__device__ float g_Wp4[208 * 2016];
__device__ float  g_deg[NN];
__device__ float  g_dis[NN];
__device__ int    g_cnt[NN];
__device__ int    g_rowptr[NN + 1];
__device__ int    g_cursor[NN];
__device__ int    g_bsum[256];
__device__ int    g_boff[256];
__device__ float2 g_cv[EE];

// ---------------- f32x2 helpers ----------------
__device__ __forceinline__ ull fma2(ull a, ull b, ull c) {
    ull d;
    asm("fma.rn.f32x2 %0, %1, %2, %3;" : "=l"(d) : "l"(a), "l"(b), "l"(c));
    return d;
}
__device__ __forceinline__ ull dup2(float v) {
    ull d;
    asm("mov.b64 %0, {%1, %1};" : "=l"(d) : "f"(v));
    return d;
}
__device__ __forceinline__ float2 unpack2(ull v) {
    float2 r;
    asm("mov.b64 {%0, %1}, %2;" : "=f"(r.x), "=f"(r.y) : "l"(v));
    return r;
}

// ---------------- CSR build ----------------
__global__ void k_zero_nodes() {
    int i = blockIdx.x * blockDim.x + threadIdx.x;
    if (i < NN) { g_deg[i] = 0.f; g_cnt[i] = 0; }
}
__global__ void k_degcnt(const int* __restrict__ ei, const float* __restrict__ ew) {
    int e = blockIdx.x * blockDim.x + threadIdx.x;
    if (e < EE) {
        int d = ei[EE + e];
        atomicAdd(&g_deg[d], ew[e]);
        atomicAdd(&g_cnt[d], 1);
    }
}
__global__ void k_dis() {
    int i = blockIdx.x * blockDim.x + threadIdx.x;
    if (i < NN) {
        float d = g_deg[i];
        g_dis[i] = (d > 0.f) ? rsqrtf(d) : 0.f;
    }
}
__global__ void k_bsum() {
    __shared__ int sh[256];
    int t = threadIdx.x, i = blockIdx.x * 256 + t;
    sh[t] = (i < NN) ? g_cnt[i] : 0;
    __syncthreads();
    for (int o = 128; o; o >>= 1) {
        if (t < o) sh[t] += sh[t + o];
        __syncthreads();
    }
    if (!t) g_bsum[blockIdx.x] = sh[0];
}
__global__ void k_bscan() {
    __shared__ int sh[256];
    int t = threadIdx.x;
    int v = (t < SBLK) ? g_bsum[t] : 0;
    sh[t] = v;
    __syncthreads();
    for (int o = 1; o < 256; o <<= 1) {
        int u = (t >= o) ? sh[t - o] : 0;
        __syncthreads();
        sh[t] += u;
        __syncthreads();
    }
    if (t < SBLK) g_boff[t] = sh[t] - v;
}
__global__ void k_wptr() {
    __shared__ int sh[256];
    int t = threadIdx.x, i = blockIdx.x * 256 + t;
    int v = (i < NN) ? g_cnt[i] : 0;
    sh[t] = v;
    __syncthreads();
    for (int o = 1; o < 256; o <<= 1) {
        int u = (t >= o) ? sh[t - o] : 0;
        __syncthreads();
        sh[t] += u;
        __syncthreads();
    }
    int excl = sh[t] - v + g_boff[blockIdx.x];
    if (i < NN) {
        g_rowptr[i] = excl;
        g_cursor[i] = excl;
        if (i == NN - 1) g_rowptr[NN] = excl + v;
    }
}
__global__ void k_scatter(const int* __restrict__ ei, const float* __restrict__ ew) {
    int e = blockIdx.x * blockDim.x + threadIdx.x;
    if (e < EE) {
        int s = ei[e];
        int d = ei[EE + e];
        int p = atomicAdd(&g_cursor[d], 1);
        float2 cv;
        cv.x = __int_as_float(s);
        cv.y = g_dis[s] * ew[e] * g_dis[d];
        g_cv[p] = cv;
    }
}

// ---------------- vector propagation: warp/node, CH 32-wide chunks -----------
template <int CH, bool ADD>
__global__ void __launch_bounds__(256) k_prop(const float* __restrict__ hin, int rsi,
                                              float* __restrict__ hout, int rso,
                                              const float* __restrict__ addp, int rsa) {
    int w = (blockIdx.x * 256 + threadIdx.x) >> 5;
    if (w >= NN) return;
    int lane = threadIdx.x & 31;
    int beg = g_rowptr[w], end = g_rowptr[w + 1];
    float acc[CH];
    if (ADD) {
        const float* ap = addp + (size_t)w * rsa + lane;
#pragma unroll
        for (int t = 0; t < CH; ++t) acc[t] = __ldg(ap + 32 * t);
    } else {
#pragma unroll
        for (int t = 0; t < CH; ++t) acc[t] = 0.f;
    }
    int p = beg;
    for (; p + 2 <= end; p += 2) {
        float2 cv0 = __ldg(&g_cv[p]);
        float2 cv1 = __ldg(&g_cv[p + 1]);
        const float* r0 = hin + (size_t)__float_as_int(cv0.x) * rsi + lane;
        const float* r1 = hin + (size_t)__float_as_int(cv1.x) * rsi + lane;
#pragma unroll
        for (int t = 0; t < CH; ++t) acc[t] += cv0.y * __ldg(r0 + 32 * t);
#pragma unroll
        for (int t = 0; t < CH; ++t) acc[t] += cv1.y * __ldg(r1 + 32 * t);
    }
    if (p < end) {
        float2 cv = __ldg(&g_cv[p]);
        const float* r = hin + (size_t)__float_as_int(cv.x) * rsi + lane;
#pragma unroll
        for (int t = 0; t < CH; ++t) acc[t] += cv.y * __ldg(r + 32 * t);
    }
    float* o = hout + (size_t)w * rso + lane;
#pragma unroll
    for (int t = 0; t < CH; ++t) o[32 * t] = acc[t];
}

// ---------------- scalar propagation ----------------
template <bool ADD>
__global__ void __launch_bounds__(256) k_sprop(const float* __restrict__ hold,
                                               float* __restrict__ hnew,
                                               const float* __restrict__ addp) {
    int w = (blockIdx.x * 256 + threadIdx.x) >> 5;
    if (w >= NN) return;
    int lane = threadIdx.x & 31;
    int beg = g_rowptr[w], end = g_rowptr[w + 1];
    float s = 0.f;
    for (int p = beg + lane; p < end; p += 32) {
        float2 cv = __ldg(&g_cv[p]);
        s += cv.y * __ldg(&hold[__float_as_int(cv.x)]);
    }
#pragma unroll
    for (int o = 16; o; o >>= 1) s += __shfl_xor_sync(0xffffffffu, s, o);
    if (lane == 0) hnew[w] = ADD ? (s + addp[w]) : s;
}

__global__ void k_seed1(const float* __restrict__ x) {
    int i = blockIdx.x * blockDim.x + threadIdx.x;
    if (i < NN) g_S1[i] = x[i];
}

// ---------------- GEMM with packed f32x2 FMA ----------------
// D[MxCout] (+bias,relu) = H[RPAD x Cin, stride sH] @ B[Cin x Cout]
#define BM 128
#define BN 64
#define BK 16
template <int MODE>  // 0: D = r    1: D = relu(r + bias)
__global__ void __launch_bounds__(256) k_gemm(const float* __restrict__ H, int sH, int Cin,
                                              const float* __restrict__ B, int Cout,
                                              float* __restrict__ D, int sD,
                                              const float* __restrict__ bias) {
    __shared__ float As[BK][BM + 8];   // +8 keeps 16B row phase
    __shared__ ull   Bs2[BK][BN];      // duplicated pairs {b,b}
    int tid = threadIdx.x;
    int m0 = blockIdx.x * BM, n0 = blockIdx.y * BN;
    int tm = tid >> 4, tn = tid & 15;
    ull acc[4][4];
#pragma unroll
    for (int i = 0; i < 4; ++i)
#pragma unroll
        for (int j = 0; j < 4; ++j) acc[i][j] = 0ull;

    for (int k0 = 0; k0 < Cin; k0 += BK) {
        {   // A tile (rows padded; vector over-read within row is safe)
            int row = tid >> 2, kq = (tid & 3) * 4;
#pragma unroll
            for (int r = 0; r < 2; ++r) {
                int m = row + 64 * r;
                float4 v = *(const float4*)&H[(size_t)(m0 + m) * sH + k0 + kq];
                As[kq + 0][m] = v.x; As[kq + 1][m] = v.y;
                As[kq + 2][m] = v.z; As[kq + 3][m] = v.w;
            }
        }
        {   // B tile with guard, stored duplicated
            int n = tid & 63, kb = tid >> 6;
#pragma unroll
            for (int r = 0; r < 4; ++r) {
                int k = kb + 4 * r;
                int gn = n0 + n;
                float v = (gn < Cout) ? __ldg(&B[(size_t)(k0 + k) * Cout + gn]) : 0.f;
                Bs2[k][n] = dup2(v);
            }
        }
        __syncthreads();
#pragma unroll
        for (int kk = 0; kk < BK; ++kk) {
            ulonglong2 a01 = *(const ulonglong2*)&As[kk][tm * 8];
            ulonglong2 a23 = *(const ulonglong2*)&As[kk][tm * 8 + 4];
            ulonglong2 b01 = *(const ulonglong2*)&Bs2[kk][tn * 4];
            ulonglong2 b23 = *(const ulonglong2*)&Bs2[kk][tn * 4 + 2];
            ull av[4] = {a01.x, a01.y, a23.x, a23.y};
            ull bv[4] = {b01.x, b01.y, b23.x, b23.y};
#pragma unroll
            for (int i = 0; i < 4; ++i)
#pragma unroll
                for (int j = 0; j < 4; ++j) acc[i][j] = fma2(av[i], bv[j], acc[i][j]);
        }
        __syncthreads();
    }
#pragma unroll
    for (int i = 0; i < 4; ++i) {
#pragma unroll
        for (int j = 0; j < 4; ++j) {
            int gn = n0 + tn * 4 + j;
            if (gn >= Cout) continue;
            float2 p = unpack2(acc[i][j]);
            int gm0 = m0 + tm * 8 + 2 * i;
            float bv = (MODE == 1) ? bias[gn] : 0.f;
            if (gm0 < NN) {
                float r = p.x + bv;
                D[(size_t)gm0 * sD + gn] = (MODE == 1) ? fmaxf(r, 0.f) : r;
            }
            if (gm0 + 1 < NN) {
                float r = p.y + bv;
                D[(size_t)(gm0 + 1) * sD + gn] = (MODE == 1) ? fmaxf(r, 0.f) : r;
            }
        }
    }
}

// ---------------- L1 head: out = relu( stack(Xs1) @ W1 + b1 ) -> S2 block0 ----
__global__ void __launch_bounds__(256) k_head(const float* __restrict__ W1,
                                              const float* __restrict__ b1) {
    int w = (blockIdx.x * 256 + threadIdx.x) >> 5;
    if (w >= NN) return;
    int lane = threadIdx.x & 31;
    float xk[21];
#pragma unroll
    for (int k = 0; k < 21; ++k) xk[k] = __ldg(&g_S1[k * RPAD + w]);
    for (int c = lane; c < 60; c += 32) {
        float a = b1[c];
#pragma unroll
        for (int k = 0; k < 21; ++k) a += xk[k] * __ldg(&W1[k * 60 + c]);
        g_S2[(size_t)w * 1344 + c] = fmaxf(a, 0.f);
    }
}

// ---------------- L5: Y5[k][n] = x5[n,:] . W5[k,:] ----------------
__global__ void __launch_bounds__(256) k_y5(const float* __restrict__ W5) {
    int w = (blockIdx.x * 256 + threadIdx.x) >> 5;
    if (w >= NN) return;
    int lane = threadIdx.x & 31;
    const float* xr = g_P0 + (size_t)w * 96;
    float x0 = xr[lane], x1 = xr[32 + lane];
    float x2 = (lane < 16) ? xr[64 + lane] : 0.f;
#pragma unroll
    for (int k = 0; k < 21; ++k) {
        float s = x0 * __ldg(&W5[k * 80 + lane]) + x1 * __ldg(&W5[k * 80 + 32 + lane]);
        if (lane < 16) s += x2 * __ldg(&W5[k * 80 + 64 + lane]);
#pragma unroll
        for (int o = 16; o; o >>= 1) s += __shfl_xor_sync(0xffffffffu, s, o);
        if (lane == 0) g_S1[k * RPAD + w] = s;
    }
}

// ---------------- misc ----------------
__global__ void __launch_bounds__(256) k_relu_b(const float* __restrict__ src, int si,
                                                float* __restrict__ dst, int so, int C,
                                                const float* __restrict__ bias) {
    int w = (blockIdx.x * 256 + threadIdx.x) >> 5;
    if (w >= NN) return;
    int lane = threadIdx.x & 31;
    for (int c = lane; c < C; c += 32) {
        float v = src[(size_t)w * si + c] + (bias ? bias[c] : 0.f);
        dst[(size_t)w * so + c] = fmaxf(v, 0.f);
    }
}
__global__ void k_sigmoid(const float* __restrict__ t, const float* __restrict__ b,
                          float* __restrict__ out) {
    int i = blockIdx.x * blockDim.x + threadIdx.x;
    if (i < NN) out[i] = 1.f / (1.f + expf(-(t[i] + b[0])));
}

// ---------------- W padding/permutation preps ----------------
__global__ void k_wp2(const float* __restrict__ W) {   // [21,60,100] -> [1344,100]
    int idx = blockIdx.x * blockDim.x + threadIdx.x;
    if (idx >= 1344 * 100) return;
    int row = idx / 100, n = idx % 100;
    int kb = row >> 6, i = row & 63;
    g_Wp2[idx] = (i < 60) ? __ldg(&W[kb * 6000 + i * 100 + n]) : 0.f;
}
__global__ void k_wp3(const float* __restrict__ W) {   // [21,100,200] -> [2688,200]
    int idx = blockIdx.x * blockDim.x + threadIdx.x;
    if (idx >= 2688 * 200) return;
    int row = idx / 200, n = idx % 200;
    int kb = row >> 7, i = row & 127;
    g_Wp3[idx] = (i < 100) ? __ldg(&W[kb * 20000 + i * 200 + n]) : 0.f;
}
__global__ void k_wp4(const float* __restrict__ W) {   // [21,200,80] -> [208, 21*96]
    int idx = blockIdx.x * blockDim.x + threadIdx.x;
    if (idx >= 208 * 2016) return;
    int i = idx / 2016, c = idx % 2016;
    int k = c / 96, j = c % 96;
    g_Wp4[idx] = (i < 200 && j < 80) ? __ldg(&W[k * 16000 + i * 80 + j]) : 0.f;
}

// ---------------- host ----------------
extern "C" void kernel_launch(void* const* d_in, const int* in_sizes, int n_in,
                              void* d_out, int out_size) {
    const float* x  = (const float*)d_in[0];
    const int*   ei = (const int*)d_in[1];
    const float* ew = (const float*)d_in[2];
    const float* Wl[5]; const float* bl[5];
    for (int l = 0; l < 5; ++l) {
        Wl[l] = (const float*)d_in[3 + 2 * l];
        bl[l] = (const float*)d_in[4 + 2 * l];
    }
    float* out = (float*)d_out;

    float *S1, *S2, *S3, *P0, *P1, *P2, *Wp2, *Wp3, *Wp4;
    cudaGetSymbolAddress((void**)&S1, g_S1);
    cudaGetSymbolAddress((void**)&S2, g_S2);
    cudaGetSymbolAddress((void**)&S3, g_S3);
    cudaGetSymbolAddress((void**)&P0, g_P0);
    cudaGetSymbolAddress((void**)&P1, g_P1);
    cudaGetSymbolAddress((void**)&P2, g_P2);
    cudaGetSymbolAddress((void**)&Wp2, g_Wp2);
    cudaGetSymbolAddress((void**)&Wp3, g_Wp3);
    cudaGetSymbolAddress((void**)&Wp4, g_Wp4);

    const int WG = (NN * 32 + 255) / 256;   // warp-per-node grid

    // ---- CSR build (coalesced multi-block scan) ----
    k_zero_nodes<<<(NN + 255) / 256, 256>>>();
    k_degcnt<<<(EE + 255) / 256, 256>>>(ei, ew);
    k_dis<<<(NN + 255) / 256, 256>>>();
    k_bsum<<<SBLK, 256>>>();
    k_bscan<<<1, 256>>>();
    k_wptr<<<SBLK, 256>>>();
    k_scatter<<<(EE + 255) / 256, 256>>>(ei, ew);

    // ---- W preps ----
    k_wp2<<<(1344 * 100 + 255) / 256, 256>>>(Wl[1]);
    k_wp3<<<(2688 * 200 + 255) / 256, 256>>>(Wl[2]);
    k_wp4<<<(208 * 2016 + 255) / 256, 256>>>(Wl[3]);

    // ---- layer 1: scalar hop stack + fused head GEMV (-> S2 block0, relu) ----
    k_seed1<<<(NN + 255) / 256, 256>>>(x);
    for (int k = 1; k <= KH; ++k)
        k_sprop<false><<<WG, 256>>>(S1 + (k - 1) * RPAD, S1 + k * RPAD, 0);
    k_head<<<WG, 256>>>(Wl[0], bl[0]);

    // ---- layer 2: stack 21x64 in S2, one GEMM [N,1344]@[1344,100] -> S3 blk0 ----
    for (int k = 1; k <= KH; ++k)
        k_prop<2, false><<<WG, 256>>>(S2 + (k - 1) * 64, 1344, S2 + k * 64, 1344, 0, 0);
    {
        dim3 g(RPAD / BM, (100 + BN - 1) / BN);
        k_gemm<1><<<g, 256>>>(S2, 1344, 1344, Wp2, 100, S3, 2688, bl[1]);
    }

    // ---- layer 3: stack 21x128 in S3, one GEMM [N,2688]@[2688,200] -> P0 ----
    for (int k = 1; k <= KH; ++k)
        k_prop<4, false><<<WG, 256>>>(S3 + (k - 1) * 128, 2688, S3 + k * 128, 2688, 0, 0);
    {
        dim3 g(RPAD / BM, (200 + BN - 1) / BN);
        k_gemm<1><<<g, 256>>>(S3, 2688, 2688, Wp3, 200, P0, 224, bl[2]);
    }

    // ---- layer 4: one GEMM Y=[N,208]@[208,2016] -> S3-as-Y, Horner props ----
    {
        dim3 g(RPAD / BM, (2016 + BN - 1) / BN);
        k_gemm<0><<<g, 256>>>(P0, 224, 208, Wp4, 2016, S3, 2016, 0);
    }
    {
        float* cur = P1; float* nxt = P2;
        const float* hin = S3 + 20 * 96;
        int rsi = 2016;
        for (int k = KH - 1; k >= 0; --k) {
            k_prop<3, true><<<WG, 256>>>(hin, rsi, cur, 96, S3 + k * 96, 2016);
            hin = cur; rsi = 96;
            float* t = cur; cur = nxt; nxt = t;
        }
        // final state is in `hin` (last written buffer)
        k_relu_b<<<WG, 256>>>(hin, 96, P0, 96, 80, bl[3]);
    }

    // ---- layer 5: Y5 [21][N] then scalar Horner, sigmoid ----
    k_y5<<<WG, 256>>>(Wl[4]);
    {
        float* cur = P1; float* nxt = P2;
        const float* hold = S1 + 20 * RPAD;
        for (int k = KH - 1; k >= 0; --k) {
            k_sprop<true><<<WG, 256>>>(hold, cur, S1 + k * RPAD);
            hold = cur;
            float* t = cur; cur = nxt; nxt = t;
        }
        k_sigmoid<<<(NN + 255) / 256, 256>>>(hold, bl[4], out);
    }
}